// round 9
// baseline (speedup 1.0000x reference)
#include <cuda_runtime.h>
#include <cuda_fp16.h>
#include <math.h>
#include <stdint.h>

#define B_   4
#define S_   4096
#define E_   2048
#define NH_  16
#define HD_  128
#define MTOT (B_ * S_)       /* 16384 */
#define NHEADS (B_ * NH_)    /* 64 */
#define KSPLIT 4

typedef __half h16;

// ---------------- scratch (device globals; no runtime allocation) ----------------
__device__ h16   g_x  [(size_t)MTOT * E_];
__device__ h16   g_wq [(size_t)E_ * E_],   g_wk [(size_t)E_ * E_];
__device__ h16   g_wv [(size_t)E_ * E_],   g_wf [(size_t)E_ * E_];
__device__ h16   g_q  [(size_t)MTOT * E_];
__device__ h16   g_Kt [(size_t)NHEADS * HD_ * S_];
__device__ h16   g_Vt [(size_t)NHEADS * HD_ * S_];
__device__ float g_kkp [KSPLIT * NHEADS * HD_ * HD_];
__device__ float g_ktvp[KSPLIT * NHEADS * HD_ * HD_];
__device__ h16   g_sT [NHEADS * HD_ * HD_];
__device__ h16   g_a  [(size_t)MTOT * E_];

// =========================== helpers ==============================================
__device__ __forceinline__ uint32_t smem_u32(const void* p) {
    return (uint32_t)__cvta_generic_to_shared(p);
}
__device__ __forceinline__ uint32_t pack2h(h16 a, h16 b) {
    return (uint32_t)__half_as_ushort(a) | ((uint32_t)__half_as_ushort(b) << 16);
}

#define CP_COMMIT() asm volatile("cp.async.commit_group;" ::: "memory")
#define CP_WAIT(n)  asm volatile("cp.async.wait_group %0;" :: "n"(n) : "memory")

__device__ __forceinline__ void cpa16(uint32_t s, const void* g) {
    asm volatile("cp.async.cg.shared.global [%0], [%1], 16;" :: "r"(s), "l"(g));
}
__device__ __forceinline__ void ldsm4(uint32_t (&r)[4], uint32_t a) {
    asm volatile("ldmatrix.sync.aligned.m8n8.x4.shared.b16 {%0,%1,%2,%3}, [%4];"
                 : "=r"(r[0]), "=r"(r[1]), "=r"(r[2]), "=r"(r[3]) : "r"(a));
}
__device__ __forceinline__ void mma_f16(float (&c)[4], const uint32_t (&a)[4],
                                        uint32_t b0, uint32_t b1) {
    asm volatile("mma.sync.aligned.m16n8k16.row.col.f32.f16.f16.f32 "
        "{%0,%1,%2,%3}, {%4,%5,%6,%7}, {%8,%9}, {%0,%1,%2,%3};"
        : "+f"(c[0]), "+f"(c[1]), "+f"(c[2]), "+f"(c[3])
        : "r"(a[0]), "r"(a[1]), "r"(a[2]), "r"(a[3]), "r"(b0), "r"(b1));
}

// =========================== mma GEMM machinery ===================================
// Block tile 128x128x64, 8 warps (2 M x 4 N), warp tile 64x32, single fp16 chain.
// smem tile: 128 rows x 64 halfs = 128B rows, SW128 XOR-swizzled.
#define TILE_BYTES 16384             /* 128 * 128B */
#define STAGE_BYTES (2 * TILE_BYTES) /* A | B = 32KB */
#define NSTAGE 6

__device__ __forceinline__ uint32_t swz(uint32_t row, uint32_t cb) {
    return row * 128 + (cb ^ ((row & 7) << 4));
}
__device__ __forceinline__ void load_tile64(uint32_t sbase, const h16* g, int ldg, int tid) {
    #pragma unroll
    for (int t = 0; t < 4; t++) {
        int idx = tid + t * 256;
        int r = idx >> 3, c = idx & 7;
        cpa16(sbase + swz(r, c * 16), g + (size_t)r * ldg + c * 8);
    }
}
__device__ __forceinline__ void stage_load(uint32_t sbase,
    const h16* A, int lda, const h16* Bs, int ldb, int tid)
{
    load_tile64(sbase,              A,  lda, tid);
    load_tile64(sbase + TILE_BYTES, Bs, ldb, tid);
}

// one 128x128x64 stage, 1 chain
__device__ __forceinline__ void compute_stage(uint32_t sbase, int wm, int wn, int lane,
                                              float (&acc)[4][4][4])
{
    const uint32_t sA = sbase, sB = sbase + TILE_BYTES;
    const int arow = wm * 64 + (lane & 15);
    const uint32_t acbx = (lane & 16) ? 16 : 0;
    const int brow = wn * 32 + (lane & 7) + ((lane & 16) ? 8 : 0);
    const uint32_t bcbx = (lane & 8) ? 16 : 0;

    #pragma unroll
    for (int kk = 0; kk < 4; kk++) {
        const uint32_t acb = kk * 32 + acbx, bcb = kk * 32 + bcbx;
        uint32_t aa[4][4], bb[2][4];
        #pragma unroll
        for (int mi = 0; mi < 4; mi++)
            ldsm4(aa[mi], sA + swz(arow + mi * 16, acb));
        #pragma unroll
        for (int nj2 = 0; nj2 < 2; nj2++)
            ldsm4(bb[nj2], sB + swz(brow + nj2 * 16, bcb));
        #pragma unroll
        for (int mi = 0; mi < 4; mi++)
            #pragma unroll
            for (int nj = 0; nj < 4; nj++) {
                const int j2 = nj >> 1, jo = (nj & 1) * 2;
                mma_f16(acc[mi][nj], aa[mi], bb[j2][jo], bb[j2][jo + 1]);
            }
    }
}

// pipelined mainloop over KT k-tiles of 64, 6-stage (192KB)
__device__ __forceinline__ void run_mainloop(uint32_t sm,
    const h16* pA, int lda, const h16* pB, int ldb, int KT,
    int wm, int wn, int lane, int tid, float (&acc)[4][4][4])
{
    #pragma unroll
    for (int p = 0; p < NSTAGE - 1; p++) {
        if (p < KT)
            stage_load(sm + p * STAGE_BYTES, pA + p * 64, lda, pB + p * 64, ldb, tid);
        CP_COMMIT();
    }
    for (int i = 0; i < KT; i++) {
        CP_WAIT(NSTAGE - 2);
        __syncthreads();
        if (i + NSTAGE - 1 < KT) {
            const int k0 = (i + NSTAGE - 1) * 64, slot = (i + NSTAGE - 1) % NSTAGE;
            stage_load(sm + slot * STAGE_BYTES, pA + k0, lda, pB + k0, ldb, tid);
        }
        CP_COMMIT();
        compute_stage(sm + (i % NSTAGE) * STAGE_BYTES, wm, wn, lane, acc);
    }
}

#define ACC_INIT(acc) \
    _Pragma("unroll") for (int a_ = 0; a_ < 4; a_++) \
    _Pragma("unroll") for (int b_ = 0; b_ < 4; b_++) \
    _Pragma("unroll") for (int c_ = 0; c_ < 4; c_++) acc[a_][b_][c_] = 0.f;

// =========================== conversion kernels ===================================
__global__ void conv_h_kernel(const float* __restrict__ in) {
    size_t i = ((size_t)blockIdx.x * 256 + threadIdx.x) * 4;
    float4 v = *(const float4*)(in + i);
    *(uint2*)(g_x + i) = make_uint2(
        pack2h(__float2half_rn(v.x), __float2half_rn(v.y)),
        pack2h(__float2half_rn(v.z), __float2half_rn(v.w)));
}

// W[K x N] fp32 -> Wt[N x K] fp16 (transpose); z selects which weight
__global__ void conv_T_kernel(const float* __restrict__ W0, const float* __restrict__ W1,
                              const float* __restrict__ W2, const float* __restrict__ W3) {
    __shared__ float t[32][33];
    const int z = blockIdx.z;
    const float* W = (z == 0) ? W0 : (z == 1) ? W1 : (z == 2) ? W2 : W3;
    h16* wt = (z == 0) ? g_wq : (z == 1) ? g_wk : (z == 2) ? g_wv : g_wf;
    const int n0 = blockIdx.x * 32, k0 = blockIdx.y * 32;
    const int tx = threadIdx.x, ty = threadIdx.y;
    #pragma unroll
    for (int j = 0; j < 4; j++)
        t[ty + 8 * j][tx] = W[(size_t)(k0 + ty + 8 * j) * E_ + n0 + tx];
    __syncthreads();
    #pragma unroll
    for (int j = 0; j < 4; j++)
        wt[(size_t)(n0 + ty + 8 * j) * E_ + k0 + tx] = __float2half_rn(t[tx][ty + 8 * j]);
}

// =========================== fused QKV GEMM =======================================
// z=0: Q -> row-major fp16; z=1: K -> transposed fp16; z=2: V -> transposed fp16
__global__ __launch_bounds__(256, 1) void gemm_qkv(
    const float* __restrict__ bq, const float* __restrict__ bk,
    const float* __restrict__ bv)
{
    extern __shared__ char smraw[];
    const uint32_t sm = (smem_u32(smraw) + 127) & ~127u;
    const int tid = threadIdx.x, lane = tid & 31, wid = tid >> 5;
    const int wm = wid >> 2, wn = wid & 3;
    const int m0 = blockIdx.y * 128, n0 = blockIdx.x * 128;
    const int z = blockIdx.z;

    const h16* Bp = (z == 0) ? g_wq : (z == 1) ? g_wk : g_wv;
    const float* bias = (z == 0) ? bq : (z == 1) ? bk : bv;

    float acc[4][4][4];
    ACC_INIT(acc)

    run_mainloop(sm, g_x + (size_t)m0 * E_, E_, Bp + (size_t)n0 * E_, E_, E_ / 64,
                 wm, wn, lane, tid, acc);

    const int rb = wm * 64 + (lane >> 2);
    const int cb = wn * 32 + (lane & 3) * 2;

    if (z == 0) {
        #pragma unroll
        for (int mi = 0; mi < 4; mi++)
            #pragma unroll
            for (int nj = 0; nj < 4; nj++) {
                const int r = m0 + rb + mi * 16;
                const int c = n0 + cb + nj * 8;
                const float b0 = bias[c], b1 = bias[c + 1];
                *(uint32_t*)(g_q + (size_t)r * E_ + c) =
                    pack2h(__float2half_rn(acc[mi][nj][0] + b0),
                           __float2half_rn(acc[mi][nj][1] + b1));
                *(uint32_t*)(g_q + (size_t)(r + 8) * E_ + c) =
                    pack2h(__float2half_rn(acc[mi][nj][2] + b0),
                           __float2half_rn(acc[mi][nj][3] + b1));
            }
        return;
    }

    // transposed epilogue via smem bounce (pitch 129 floats)
    __syncthreads();
    float* sT = (float*)(smraw) + 32;
    #pragma unroll
    for (int mi = 0; mi < 4; mi++)
        #pragma unroll
        for (int nj = 0; nj < 4; nj++) {
            const int r = rb + mi * 16;
            const int c = cb + nj * 8;
            const float b0 = bias[n0 + c], b1 = bias[n0 + c + 1];
            sT[r * 129 + c]           = acc[mi][nj][0] + b0;
            sT[r * 129 + c + 1]       = acc[mi][nj][1] + b1;
            sT[(r + 8) * 129 + c]     = acc[mi][nj][2] + b0;
            sT[(r + 8) * 129 + c + 1] = acc[mi][nj][3] + b1;
        }
    __syncthreads();

    h16* dst = (z == 1) ? g_Kt : g_Vt;
    const int e = tid >> 1, sh = (tid & 1) * 64;
    const int bB = m0 / S_, sInB = (m0 % S_) + sh;
    const size_t grow = ((size_t)(bB * E_ + n0 + e)) * S_ + sInB;

    uint32_t hw[32];
    #pragma unroll
    for (int q = 0; q < 32; q++) {
        float v0 = sT[(sh + 2 * q) * 129 + e];
        float v1 = sT[(sh + 2 * q + 1) * 129 + e];
        hw[q] = pack2h(__float2half_rn(v0), __float2half_rn(v1));
    }
    #pragma unroll
    for (int q = 0; q < 8; q++)
        *(uint4*)(dst + grow + q * 8) = make_uint4(hw[q*4], hw[q*4+1], hw[q*4+2], hw[q*4+3]);
}

// =========================== final GEMM ===========================================
__global__ __launch_bounds__(256, 1) void gemm_fc(const float* __restrict__ bias,
                                                  float* __restrict__ outF)
{
    extern __shared__ char smraw[];
    const uint32_t sm = (smem_u32(smraw) + 127) & ~127u;
    const int tid = threadIdx.x, lane = tid & 31, wid = tid >> 5;
    const int wm = wid >> 2, wn = wid & 3;
    const int m0 = blockIdx.y * 128, n0 = blockIdx.x * 128;

    float acc[4][4][4];
    ACC_INIT(acc)

    run_mainloop(sm, g_a + (size_t)m0 * E_, E_, g_wf + (size_t)n0 * E_, E_, E_ / 64,
                 wm, wn, lane, tid, acc);

    const int row_base = m0 + wm * 64 + (lane >> 2);
    const int col_base = n0 + wn * 32 + (lane & 3) * 2;
    #pragma unroll
    for (int mi = 0; mi < 4; mi++)
        #pragma unroll
        for (int nj = 0; nj < 4; nj++) {
            const int r = row_base + mi * 16;
            const int c = col_base + nj * 8;
            const float b0 = bias[c], b1 = bias[c + 1];
            *(float2*)(outF + (size_t)r * E_ + c) =
                make_float2(acc[mi][nj][0] + b0, acc[mi][nj][1] + b1);
            *(float2*)(outF + (size_t)(r + 8) * E_ + c) =
                make_float2(acc[mi][nj][2] + b0, acc[mi][nj][3] + b1);
        }
}

// =========================== K^T K / K^T V (split-K x4) ===========================
__global__ __launch_bounds__(256, 1) void ktk_mma()
{
    extern __shared__ char smraw[];
    const uint32_t sm = (smem_u32(smraw) + 127) & ~127u;
    const int tid = threadIdx.x, lane = tid & 31, wid = tid >> 5;
    const int wm = wid >> 2, wn = wid & 3;
    const int head = blockIdx.x, which = blockIdx.y, ks = blockIdx.z;

    const size_t hb = (size_t)head * HD_ * S_ + ks * (S_ / KSPLIT);
    const h16* pA = g_Kt + hb;
    const h16* pB = (which ? g_Vt : g_Kt) + hb;
    float* out = (which ? g_ktvp : g_kkp) + ((size_t)ks * NHEADS + head) * HD_ * HD_;

    float acc[4][4][4];
    ACC_INIT(acc)

    run_mainloop(sm, pA, S_, pB, S_, (S_ / KSPLIT) / 64, wm, wn, lane, tid, acc);

    const int row_base = wm * 64 + (lane >> 2);
    const int col_base = wn * 32 + (lane & 3) * 2;
    #pragma unroll
    for (int mi = 0; mi < 4; mi++)
        #pragma unroll
        for (int nj = 0; nj < 4; nj++) {
            const int r = row_base + mi * 16;
            const int c = col_base + nj * 8;
            *(float2*)(out + (size_t)r * HD_ + c) =
                make_float2(acc[mi][nj][0], acc[mi][nj][1]);
            *(float2*)(out + (size_t)(r + 8) * HD_ + c) =
                make_float2(acc[mi][nj][2], acc[mi][nj][3]);
        }
}

// =========================== solve + softmax (fp32 SIMT) ==========================
#define LDAUG 257
__global__ __launch_bounds__(256) void solve_softmax_kernel(const float* __restrict__ alpha)
{
    extern __shared__ float sAug[];
    __shared__ float facs[128];
    const int head = blockIdx.x;
    const int tid = threadIdx.x;
    const size_t hoff = (size_t)head * HD_ * HD_;
    const size_t pstride = (size_t)NHEADS * HD_ * HD_;
    const float a = alpha[0];

    for (int idx = tid; idx < HD_ * HD_; idx += 256) {
        int r = idx >> 7, c = idx & 127;
        float skk  = g_kkp [hoff + idx] + g_kkp [pstride + hoff + idx]
                   + g_kkp [2 * pstride + hoff + idx] + g_kkp [3 * pstride + hoff + idx];
        float sktv = g_ktvp[hoff + idx] + g_ktvp[pstride + hoff + idx]
                   + g_ktvp[2 * pstride + hoff + idx] + g_ktvp[3 * pstride + hoff + idx];
        sAug[r * LDAUG + c]       = skk + (r == c ? a : 0.f);
        sAug[r * LDAUG + 128 + c] = sktv;
    }
    __syncthreads();

    for (int k = 0; k < HD_; k++) {
        if (tid < 128) facs[tid] = sAug[tid * LDAUG + k];
        __syncthreads();
        float pivc = sAug[k * LDAUG + tid] / facs[k];
        sAug[k * LDAUG + tid] = pivc;
        __syncthreads();
        #pragma unroll 4
        for (int r = 0; r < HD_; r++)
            if (r != k) sAug[r * LDAUG + tid] -= facs[r] * pivc;
        __syncthreads();
    }

    const int warp = tid >> 5, lane = tid & 31;
    for (int r = warp; r < HD_; r += 8) {
        float vals[4];
        float mx = -1e30f;
        #pragma unroll
        for (int t = 0; t < 4; t++) {
            vals[t] = sAug[r * LDAUG + 128 + lane + 32 * t];
            mx = fmaxf(mx, vals[t]);
        }
        #pragma unroll
        for (int o = 16; o; o >>= 1) mx = fmaxf(mx, __shfl_xor_sync(0xffffffffu, mx, o));
        float sum = 0.f;
        #pragma unroll
        for (int t = 0; t < 4; t++) { vals[t] = expf(vals[t] - mx); sum += vals[t]; }
        #pragma unroll
        for (int o = 16; o; o >>= 1) sum += __shfl_xor_sync(0xffffffffu, sum, o);
        float inv = 1.f / sum;
        #pragma unroll
        for (int t = 0; t < 4; t++) {
            int e = lane + 32 * t;
            g_sT[hoff + e * HD_ + r] = __float2half_rn(vals[t] * inv);  // score^T[e][d=r]
        }
    }
}

// =========================== attn = Q @ score =====================================
__global__ __launch_bounds__(256, 1) void attn_mma()
{
    extern __shared__ char smraw[];
    const uint32_t sm = (smem_u32(smraw) + 127) & ~127u;
    const int tid = threadIdx.x, lane = tid & 31, wid = tid >> 5;
    const int wm = wid >> 2, wn = wid & 3;
    const int head = blockIdx.x, stile = blockIdx.y;
    const int bb = head >> 4, h = head & 15;
    const size_t arow0 = (size_t)(bb * S_ + stile * 128);

    const h16* pA = g_q + arow0 * E_ + h * 128;
    const h16* pB = g_sT + (size_t)head * HD_ * HD_;

    float acc[4][4][4];
    ACC_INIT(acc)

    run_mainloop(sm, pA, E_, pB, HD_, HD_ / 64, wm, wn, lane, tid, acc);

    const int row_base = wm * 64 + (lane >> 2);
    const int col_base = h * 128 + wn * 32 + (lane & 3) * 2;
    #pragma unroll
    for (int mi = 0; mi < 4; mi++)
        #pragma unroll
        for (int nj = 0; nj < 4; nj++) {
            const size_t r = arow0 + row_base + mi * 16;
            const int c = col_base + nj * 8;
            *(uint32_t*)(g_a + r * E_ + c) =
                pack2h(__float2half_rn(acc[mi][nj][0]), __float2half_rn(acc[mi][nj][1]));
            *(uint32_t*)(g_a + (r + 8) * E_ + c) =
                pack2h(__float2half_rn(acc[mi][nj][2]), __float2half_rn(acc[mi][nj][3]));
        }
}

// =================================================================================
extern "C" void kernel_launch(void* const* d_in, const int* in_sizes, int n_in,
                              void* d_out, int out_size)
{
    (void)in_sizes; (void)n_in; (void)out_size;
    const float* x     = (const float*)d_in[0];
    const float* alpha = (const float*)d_in[1];
    const float* Wq    = (const float*)d_in[2];
    const float* bq    = (const float*)d_in[3];
    const float* Wk    = (const float*)d_in[4];
    const float* bk    = (const float*)d_in[5];
    const float* Wv    = (const float*)d_in[6];
    const float* bv    = (const float*)d_in[7];
    const float* Wfc   = (const float*)d_in[8];
    const float* bfc   = (const float*)d_in[9];
    float* out = (float*)d_out;

    const int SMEM_MMA = NSTAGE * STAGE_BYTES + 1024;  // 197632
    const int SMEM_S   = 128 * LDAUG * 4;              // 131584
    cudaFuncSetAttribute(gemm_qkv, cudaFuncAttributeMaxDynamicSharedMemorySize, SMEM_MMA);
    cudaFuncSetAttribute(gemm_fc,  cudaFuncAttributeMaxDynamicSharedMemorySize, SMEM_MMA);
    cudaFuncSetAttribute(ktk_mma,  cudaFuncAttributeMaxDynamicSharedMemorySize, SMEM_MMA);
    cudaFuncSetAttribute(attn_mma, cudaFuncAttributeMaxDynamicSharedMemorySize, SMEM_MMA);
    cudaFuncSetAttribute(solve_softmax_kernel, cudaFuncAttributeMaxDynamicSharedMemorySize, SMEM_S);

    // 1) x -> fp16
    conv_h_kernel<<<(int)((size_t)MTOT * E_ / 4 / 256), 256>>>(x);
    // 2) transpose weights -> [N x K] fp16 (all 4 in one launch)
    dim3 tb(32, 8), tg(E_ / 32, E_ / 32, 4);
    conv_T_kernel<<<tg, tb>>>(Wq, Wk, Wv, Wfc);
    // 3) fused Q/K/V projections (K,V written transposed directly)
    gemm_qkv<<<dim3(E_ / 128, MTOT / 128, 3), 256, SMEM_MMA>>>(bq, bk, bv);
    // 4) K^T K and K^T V (split-K x4 into partials)
    ktk_mma<<<dim3(NHEADS, 2, KSPLIT), 256, SMEM_MMA>>>();
    // 5) solve + softmax -> score^T fp16; sums partials on load
    solve_softmax_kernel<<<NHEADS, 256, SMEM_S>>>(alpha);
    // 6) attn = Q @ score
    attn_mma<<<dim3(NHEADS, S_ / 128), 256, SMEM_MMA>>>();
    // 7) output projection
    gemm_fc<<<dim3(E_ / 128, MTOT / 128), 256, SMEM_MMA>>>(bfc, out);
}

// round 11
// speedup vs baseline: 1.7152x; 1.7152x over previous
#include <cuda_runtime.h>
#include <cuda_fp16.h>
#include <math.h>
#include <stdint.h>

#define B_   4
#define S_   4096
#define E_   2048
#define NH_  16
#define HD_  128
#define MTOT (B_ * S_)       /* 16384 */
#define NHEADS (B_ * NH_)    /* 64 */
#define KSPLIT 4

typedef __half h16;

// ---------------- scratch (device globals; no runtime allocation) ----------------
__device__ h16   g_x  [(size_t)MTOT * E_];
__device__ h16   g_wq [(size_t)E_ * E_],   g_wk [(size_t)E_ * E_];
__device__ h16   g_wv [(size_t)E_ * E_],   g_wf [(size_t)E_ * E_];
__device__ h16   g_q  [(size_t)MTOT * E_];
__device__ h16   g_Kt [(size_t)NHEADS * HD_ * S_];
__device__ h16   g_Vt [(size_t)NHEADS * HD_ * S_];
__device__ float g_kkp [KSPLIT * NHEADS * HD_ * HD_];
__device__ float g_ktvp[KSPLIT * NHEADS * HD_ * HD_];
__device__ h16   g_sT [NHEADS * HD_ * HD_];
__device__ h16   g_a  [(size_t)MTOT * E_];

// =========================== helpers ==============================================
__device__ __forceinline__ uint32_t smem_u32(const void* p) {
    return (uint32_t)__cvta_generic_to_shared(p);
}
__device__ __forceinline__ uint32_t pack2h(h16 a, h16 b) {
    return (uint32_t)__half_as_ushort(a) | ((uint32_t)__half_as_ushort(b) << 16);
}

#define CP_COMMIT() asm volatile("cp.async.commit_group;" ::: "memory")
#define CP_WAIT(n)  asm volatile("cp.async.wait_group %0;" :: "n"(n) : "memory")

__device__ __forceinline__ void cpa16(uint32_t s, const void* g) {
    asm volatile("cp.async.cg.shared.global [%0], [%1], 16;" :: "r"(s), "l"(g));
}
__device__ __forceinline__ void ldsm4(uint32_t (&r)[4], uint32_t a) {
    asm volatile("ldmatrix.sync.aligned.m8n8.x4.shared.b16 {%0,%1,%2,%3}, [%4];"
                 : "=r"(r[0]), "=r"(r[1]), "=r"(r[2]), "=r"(r[3]) : "r"(a));
}
__device__ __forceinline__ void mma_f16(float (&c)[4], const uint32_t (&a)[4],
                                        uint32_t b0, uint32_t b1) {
    asm volatile("mma.sync.aligned.m16n8k16.row.col.f32.f16.f16.f32 "
        "{%0,%1,%2,%3}, {%4,%5,%6,%7}, {%8,%9}, {%0,%1,%2,%3};"
        : "+f"(c[0]), "+f"(c[1]), "+f"(c[2]), "+f"(c[3])
        : "r"(a[0]), "r"(a[1]), "r"(a[2]), "r"(a[3]), "r"(b0), "r"(b1));
}

// =========================== mma GEMM machinery ===================================
// Templated on MI (A-fragment rows per warp / 16): block tile (MI*32) x 128 x 64.
// 8 warps as 2(M) x 4(N); warp tile (MI*16) x 32. SW128 XOR-swizzled smem.
__device__ __forceinline__ uint32_t swz(uint32_t row, uint32_t cb) {
    return row * 128 + (cb ^ ((row & 7) << 4));
}
template<int R>
__device__ __forceinline__ void load_tileR(uint32_t sbase, const h16* g, int ldg, int tid) {
    #pragma unroll
    for (int t = 0; t < R / 32; t++) {
        int idx = tid + t * 256;
        int r = idx >> 3, c = idx & 7;
        cpa16(sbase + swz(r, c * 16), g + (size_t)r * ldg + c * 8);
    }
}
template<int MI>
__device__ __forceinline__ void stage_load(uint32_t sbase,
    const h16* A, int lda, const h16* Bs, int ldb, int tid)
{
    load_tileR<MI * 32>(sbase, A, lda, tid);
    load_tileR<128>(sbase + MI * 4096, Bs, ldb, tid);
}

template<int MI>
__device__ __forceinline__ void compute_stage(uint32_t sbase, int wm, int wn, int lane,
                                              float (&acc)[MI][4][4])
{
    const uint32_t sA = sbase, sB = sbase + MI * 4096;
    const int arow = wm * (MI * 16) + (lane & 15);
    const uint32_t acbx = (lane & 16) ? 16 : 0;
    const int brow = wn * 32 + (lane & 7) + ((lane & 16) ? 8 : 0);
    const uint32_t bcbx = (lane & 8) ? 16 : 0;

    #pragma unroll
    for (int kk = 0; kk < 4; kk++) {
        const uint32_t acb = kk * 32 + acbx, bcb = kk * 32 + bcbx;
        uint32_t bb[2][4];
        #pragma unroll
        for (int nj2 = 0; nj2 < 2; nj2++)
            ldsm4(bb[nj2], sB + swz(brow + nj2 * 16, bcb));
        #pragma unroll
        for (int mi = 0; mi < MI; mi++) {
            uint32_t aa[4];
            ldsm4(aa, sA + swz(arow + mi * 16, acb));
            #pragma unroll
            for (int nj = 0; nj < 4; nj++) {
                const int j2 = nj >> 1, jo = (nj & 1) * 2;
                mma_f16(acc[mi][nj], aa, bb[j2][jo], bb[j2][jo + 1]);
            }
        }
    }
}

template<int MI, int NST>
__device__ __forceinline__ void run_mainloop(uint32_t sm,
    const h16* pA, int lda, const h16* pB, int ldb, int KT,
    int wm, int wn, int lane, int tid, float (&acc)[MI][4][4])
{
    const uint32_t SB = MI * 4096 + 16384;
    #pragma unroll
    for (int p = 0; p < NST - 1; p++) {
        if (p < KT)
            stage_load<MI>(sm + p * SB, pA + p * 64, lda, pB + p * 64, ldb, tid);
        CP_COMMIT();
    }
    for (int i = 0; i < KT; i++) {
        CP_WAIT(NST - 2);
        __syncthreads();
        if (i + NST - 1 < KT) {
            const int k0 = (i + NST - 1) * 64, slot = (i + NST - 1) % NST;
            stage_load<MI>(sm + slot * SB, pA + k0, lda, pB + k0, ldb, tid);
        }
        CP_COMMIT();
        compute_stage<MI>(sm + (i % NST) * SB, wm, wn, lane, acc);
    }
}

#define ACC_INIT(acc, MI) \
    _Pragma("unroll") for (int a_ = 0; a_ < (MI); a_++) \
    _Pragma("unroll") for (int b_ = 0; b_ < 4; b_++) \
    _Pragma("unroll") for (int c_ = 0; c_ < 4; c_++) acc[a_][b_][c_] = 0.f;

// =========================== conversion kernels ===================================
__global__ void conv_h_kernel(const float* __restrict__ in) {
    size_t i = ((size_t)blockIdx.x * 256 + threadIdx.x) * 4;
    float4 v = *(const float4*)(in + i);
    *(uint2*)(g_x + i) = make_uint2(
        pack2h(__float2half_rn(v.x), __float2half_rn(v.y)),
        pack2h(__float2half_rn(v.z), __float2half_rn(v.w)));
}

__global__ void conv_T_kernel(const float* __restrict__ W0, const float* __restrict__ W1,
                              const float* __restrict__ W2, const float* __restrict__ W3) {
    __shared__ float t[32][33];
    const int z = blockIdx.z;
    const float* W = (z == 0) ? W0 : (z == 1) ? W1 : (z == 2) ? W2 : W3;
    h16* wt = (z == 0) ? g_wq : (z == 1) ? g_wk : (z == 2) ? g_wv : g_wf;
    const int n0 = blockIdx.x * 32, k0 = blockIdx.y * 32;
    const int tx = threadIdx.x, ty = threadIdx.y;
    #pragma unroll
    for (int j = 0; j < 4; j++)
        t[ty + 8 * j][tx] = W[(size_t)(k0 + ty + 8 * j) * E_ + n0 + tx];
    __syncthreads();
    #pragma unroll
    for (int j = 0; j < 4; j++)
        wt[(size_t)(n0 + ty + 8 * j) * E_ + k0 + tx] = __float2half_rn(t[tx][ty + 8 * j]);
}

// =========================== fused QKV GEMM (BM=256) ==============================
// z=0: Q -> row-major fp16; z=1: K -> transposed fp16; z=2: V -> transposed fp16
__global__ __launch_bounds__(256, 1) void gemm_qkv(
    const float* __restrict__ bq, const float* __restrict__ bk,
    const float* __restrict__ bv)
{
    extern __shared__ char smraw[];
    const uint32_t sm = (smem_u32(smraw) + 127) & ~127u;
    const int tid = threadIdx.x, lane = tid & 31, wid = tid >> 5;
    const int wm = wid >> 2, wn = wid & 3;
    const int m0 = blockIdx.y * 256, n0 = blockIdx.x * 128;
    const int z = blockIdx.z;

    const h16* Bp = (z == 0) ? g_wq : (z == 1) ? g_wk : g_wv;
    const float* bias = (z == 0) ? bq : (z == 1) ? bk : bv;

    float acc[8][4][4];
    ACC_INIT(acc, 8)

    run_mainloop<8, 4>(sm, g_x + (size_t)m0 * E_, E_, Bp + (size_t)n0 * E_, E_,
                       E_ / 64, wm, wn, lane, tid, acc);

    const int rb = wm * 128 + (lane >> 2);
    const int cb = wn * 32 + (lane & 3) * 2;

    if (z == 0) {
        #pragma unroll
        for (int mi = 0; mi < 8; mi++)
            #pragma unroll
            for (int nj = 0; nj < 4; nj++) {
                const int r = m0 + rb + mi * 16;
                const int c = n0 + cb + nj * 8;
                const float b0 = bias[c], b1 = bias[c + 1];
                *(uint32_t*)(g_q + (size_t)r * E_ + c) =
                    pack2h(__float2half_rn(acc[mi][nj][0] + b0),
                           __float2half_rn(acc[mi][nj][1] + b1));
                *(uint32_t*)(g_q + (size_t)(r + 8) * E_ + c) =
                    pack2h(__float2half_rn(acc[mi][nj][2] + b0),
                           __float2half_rn(acc[mi][nj][3] + b1));
            }
        return;
    }

    // transposed epilogue via smem bounce: 256 rows(s) x 128 cols(e), pitch 129
    __syncthreads();
    float* sT = (float*)(smraw) + 32;
    #pragma unroll
    for (int mi = 0; mi < 8; mi++)
        #pragma unroll
        for (int nj = 0; nj < 4; nj++) {
            const int r = rb + mi * 16;
            const int c = cb + nj * 8;
            const float b0 = bias[n0 + c], b1 = bias[n0 + c + 1];
            sT[r * 129 + c]           = acc[mi][nj][0] + b0;
            sT[r * 129 + c + 1]       = acc[mi][nj][1] + b1;
            sT[(r + 8) * 129 + c]     = acc[mi][nj][2] + b0;
            sT[(r + 8) * 129 + c + 1] = acc[mi][nj][3] + b1;
        }
    __syncthreads();

    h16* dst = (z == 1) ? g_Kt : g_Vt;
    const int e = tid >> 1, sh = (tid & 1) * 128;
    const int bB = m0 / S_, sInB = (m0 % S_) + sh;
    const size_t grow = ((size_t)(bB * E_ + n0 + e)) * S_ + sInB;

    uint32_t hw[64];
    #pragma unroll
    for (int q = 0; q < 64; q++) {
        float v0 = sT[(sh + 2 * q) * 129 + e];
        float v1 = sT[(sh + 2 * q + 1) * 129 + e];
        hw[q] = pack2h(__float2half_rn(v0), __float2half_rn(v1));
    }
    #pragma unroll
    for (int q = 0; q < 16; q++)
        *(uint4*)(dst + grow + q * 8) = make_uint4(hw[q*4], hw[q*4+1], hw[q*4+2], hw[q*4+3]);
}

// =========================== final GEMM (BM=256) ==================================
__global__ __launch_bounds__(256, 1) void gemm_fc(const float* __restrict__ bias,
                                                  float* __restrict__ outF)
{
    extern __shared__ char smraw[];
    const uint32_t sm = (smem_u32(smraw) + 127) & ~127u;
    const int tid = threadIdx.x, lane = tid & 31, wid = tid >> 5;
    const int wm = wid >> 2, wn = wid & 3;
    const int m0 = blockIdx.y * 256, n0 = blockIdx.x * 128;

    float acc[8][4][4];
    ACC_INIT(acc, 8)

    run_mainloop<8, 4>(sm, g_a + (size_t)m0 * E_, E_, g_wf + (size_t)n0 * E_, E_,
                       E_ / 64, wm, wn, lane, tid, acc);

    const int row_base = m0 + wm * 128 + (lane >> 2);
    const int col_base = n0 + wn * 32 + (lane & 3) * 2;
    #pragma unroll
    for (int mi = 0; mi < 8; mi++)
        #pragma unroll
        for (int nj = 0; nj < 4; nj++) {
            const int r = row_base + mi * 16;
            const int c = col_base + nj * 8;
            const float b0 = bias[c], b1 = bias[c + 1];
            *(float2*)(outF + (size_t)r * E_ + c) =
                make_float2(acc[mi][nj][0] + b0, acc[mi][nj][1] + b1);
            *(float2*)(outF + (size_t)(r + 8) * E_ + c) =
                make_float2(acc[mi][nj][2] + b0, acc[mi][nj][3] + b1);
        }
}

// =========================== K^T K / K^T V (split-K x4, MI=4) =====================
__global__ __launch_bounds__(256, 1) void ktk_mma()
{
    extern __shared__ char smraw[];
    const uint32_t sm = (smem_u32(smraw) + 127) & ~127u;
    const int tid = threadIdx.x, lane = tid & 31, wid = tid >> 5;
    const int wm = wid >> 2, wn = wid & 3;
    const int head = blockIdx.x, which = blockIdx.y, ks = blockIdx.z;

    const size_t hb = (size_t)head * HD_ * S_ + ks * (S_ / KSPLIT);
    const h16* pA = g_Kt + hb;
    const h16* pB = (which ? g_Vt : g_Kt) + hb;
    float* out = (which ? g_ktvp : g_kkp) + ((size_t)ks * NHEADS + head) * HD_ * HD_;

    float acc[4][4][4];
    ACC_INIT(acc, 4)

    run_mainloop<4, 6>(sm, pA, S_, pB, S_, (S_ / KSPLIT) / 64, wm, wn, lane, tid, acc);

    const int row_base = wm * 64 + (lane >> 2);
    const int col_base = wn * 32 + (lane & 3) * 2;
    #pragma unroll
    for (int mi = 0; mi < 4; mi++)
        #pragma unroll
        for (int nj = 0; nj < 4; nj++) {
            const int r = row_base + mi * 16;
            const int c = col_base + nj * 8;
            *(float2*)(out + (size_t)r * HD_ + c) =
                make_float2(acc[mi][nj][0], acc[mi][nj][1]);
            *(float2*)(out + (size_t)(r + 8) * HD_ + c) =
                make_float2(acc[mi][nj][2], acc[mi][nj][3]);
        }
}

// =========================== solve + softmax (fp32 SIMT) ==========================
#define LDAUG 257
__global__ __launch_bounds__(256) void solve_softmax_kernel(const float* __restrict__ alpha)
{
    extern __shared__ float sAug[];
    __shared__ float facs[128];
    const int head = blockIdx.x;
    const int tid = threadIdx.x;
    const size_t hoff = (size_t)head * HD_ * HD_;
    const size_t pstride = (size_t)NHEADS * HD_ * HD_;
    const float a = alpha[0];

    for (int idx = tid; idx < HD_ * HD_; idx += 256) {
        int r = idx >> 7, c = idx & 127;
        float skk  = g_kkp [hoff + idx] + g_kkp [pstride + hoff + idx]
                   + g_kkp [2 * pstride + hoff + idx] + g_kkp [3 * pstride + hoff + idx];
        float sktv = g_ktvp[hoff + idx] + g_ktvp[pstride + hoff + idx]
                   + g_ktvp[2 * pstride + hoff + idx] + g_ktvp[3 * pstride + hoff + idx];
        sAug[r * LDAUG + c]       = skk + (r == c ? a : 0.f);
        sAug[r * LDAUG + 128 + c] = sktv;
    }
    __syncthreads();

    for (int k = 0; k < HD_; k++) {
        if (tid < 128) facs[tid] = sAug[tid * LDAUG + k];
        __syncthreads();
        float pivc = sAug[k * LDAUG + tid] / facs[k];
        sAug[k * LDAUG + tid] = pivc;
        __syncthreads();
        #pragma unroll 4
        for (int r = 0; r < HD_; r++)
            if (r != k) sAug[r * LDAUG + tid] -= facs[r] * pivc;
        __syncthreads();
    }

    const int warp = tid >> 5, lane = tid & 31;
    for (int r = warp; r < HD_; r += 8) {
        float vals[4];
        float mx = -1e30f;
        #pragma unroll
        for (int t = 0; t < 4; t++) {
            vals[t] = sAug[r * LDAUG + 128 + lane + 32 * t];
            mx = fmaxf(mx, vals[t]);
        }
        #pragma unroll
        for (int o = 16; o; o >>= 1) mx = fmaxf(mx, __shfl_xor_sync(0xffffffffu, mx, o));
        float sum = 0.f;
        #pragma unroll
        for (int t = 0; t < 4; t++) { vals[t] = expf(vals[t] - mx); sum += vals[t]; }
        #pragma unroll
        for (int o = 16; o; o >>= 1) sum += __shfl_xor_sync(0xffffffffu, sum, o);
        float inv = 1.f / sum;
        #pragma unroll
        for (int t = 0; t < 4; t++) {
            int e = lane + 32 * t;
            g_sT[hoff + e * HD_ + r] = __float2half_rn(vals[t] * inv);  // score^T[e][d=r]
        }
    }
}

// =========================== attn = Q @ score (BM=256) ============================
// grid (64 heads, 16 s-tiles of 256): D[s(256)][e(128)] = q[s][:] @ scoreT^T
__global__ __launch_bounds__(256, 1) void attn_mma()
{
    extern __shared__ char smraw[];
    const uint32_t sm = (smem_u32(smraw) + 127) & ~127u;
    const int tid = threadIdx.x, lane = tid & 31, wid = tid >> 5;
    const int wm = wid >> 2, wn = wid & 3;
    const int head = blockIdx.x, stile = blockIdx.y;
    const int bb = head >> 4, h = head & 15;
    const size_t arow0 = (size_t)(bb * S_ + stile * 256);

    const h16* pA = g_q + arow0 * E_ + h * 128;
    const h16* pB = g_sT + (size_t)head * HD_ * HD_;

    float acc[8][4][4];
    ACC_INIT(acc, 8)

    run_mainloop<8, 4>(sm, pA, E_, pB, HD_, HD_ / 64, wm, wn, lane, tid, acc);

    const int row_base = wm * 128 + (lane >> 2);
    const int col_base = h * 128 + wn * 32 + (lane & 3) * 2;
    #pragma unroll
    for (int mi = 0; mi < 8; mi++)
        #pragma unroll
        for (int nj = 0; nj < 4; nj++) {
            const size_t r = arow0 + row_base + mi * 16;
            const int c = col_base + nj * 8;
            *(uint32_t*)(g_a + r * E_ + c) =
                pack2h(__float2half_rn(acc[mi][nj][0]), __float2half_rn(acc[mi][nj][1]));
            *(uint32_t*)(g_a + (r + 8) * E_ + c) =
                pack2h(__float2half_rn(acc[mi][nj][2]), __float2half_rn(acc[mi][nj][3]));
        }
}

// =================================================================================
extern "C" void kernel_launch(void* const* d_in, const int* in_sizes, int n_in,
                              void* d_out, int out_size)
{
    (void)in_sizes; (void)n_in; (void)out_size;
    const float* x     = (const float*)d_in[0];
    const float* alpha = (const float*)d_in[1];
    const float* Wq    = (const float*)d_in[2];
    const float* bq    = (const float*)d_in[3];
    const float* Wk    = (const float*)d_in[4];
    const float* bk    = (const float*)d_in[5];
    const float* Wv    = (const float*)d_in[6];
    const float* bv    = (const float*)d_in[7];
    const float* Wfc   = (const float*)d_in[8];
    const float* bfc   = (const float*)d_in[9];
    float* out = (float*)d_out;

    const int SMEM_BIG = 4 * (8 * 4096 + 16384) + 1024;   // 197632 (MI=8, 4 stages)
    const int SMEM_KTK = 6 * (4 * 4096 + 16384) + 1024;   // 197632 (MI=4, 6 stages)
    const int SMEM_S   = 128 * LDAUG * 4;                 // 131584
    cudaFuncSetAttribute(gemm_qkv, cudaFuncAttributeMaxDynamicSharedMemorySize, SMEM_BIG);
    cudaFuncSetAttribute(gemm_fc,  cudaFuncAttributeMaxDynamicSharedMemorySize, SMEM_BIG);
    cudaFuncSetAttribute(ktk_mma,  cudaFuncAttributeMaxDynamicSharedMemorySize, SMEM_KTK);
    cudaFuncSetAttribute(attn_mma, cudaFuncAttributeMaxDynamicSharedMemorySize, SMEM_BIG);
    cudaFuncSetAttribute(solve_softmax_kernel, cudaFuncAttributeMaxDynamicSharedMemorySize, SMEM_S);

    // 1) x -> fp16
    conv_h_kernel<<<(int)((size_t)MTOT * E_ / 4 / 256), 256>>>(x);
    // 2) transpose weights -> [N x K] fp16 (all 4 in one launch)
    dim3 tb(32, 8), tg(E_ / 32, E_ / 32, 4);
    conv_T_kernel<<<tg, tb>>>(Wq, Wk, Wv, Wfc);
    // 3) fused Q/K/V projections, BM=256 (K,V written transposed directly)
    gemm_qkv<<<dim3(E_ / 128, MTOT / 256, 3), 256, SMEM_BIG>>>(bq, bk, bv);
    // 4) K^T K and K^T V (split-K x4 into partials)
    ktk_mma<<<dim3(NHEADS, 2, KSPLIT), 256, SMEM_KTK>>>();
    // 5) solve + softmax -> score^T fp16; sums partials on load
    solve_softmax_kernel<<<NHEADS, 256, SMEM_S>>>(alpha);
    // 6) attn = Q @ score, BM=256
    attn_mma<<<dim3(NHEADS, S_ / 256), 256, SMEM_BIG>>>();
    // 7) output projection, BM=256
    gemm_fc<<<dim3(E_ / 128, MTOT / 256), 256, SMEM_BIG>>>(bfc, out);
}

// round 12
// speedup vs baseline: 1.7611x; 1.0268x over previous
#include <cuda_runtime.h>
#include <cuda_fp16.h>
#include <math.h>
#include <stdint.h>

#define B_   4
#define S_   4096
#define E_   2048
#define NH_  16
#define HD_  128
#define MTOT (B_ * S_)       /* 16384 */
#define NHEADS (B_ * NH_)    /* 64 */
#define KSPLIT 4

typedef __half h16;

// ---------------- scratch (device globals; no runtime allocation) ----------------
__device__ h16   g_x  [(size_t)MTOT * E_];
__device__ h16   g_wq [(size_t)E_ * E_],   g_wk [(size_t)E_ * E_];
__device__ h16   g_wv [(size_t)E_ * E_],   g_wf [(size_t)E_ * E_];
__device__ h16   g_q  [(size_t)MTOT * E_];
__device__ h16   g_Kt [(size_t)NHEADS * HD_ * S_];
__device__ h16   g_Vt [(size_t)NHEADS * HD_ * S_];
__device__ float g_kkp [KSPLIT * NHEADS * HD_ * HD_];
__device__ float g_ktvp[KSPLIT * NHEADS * HD_ * HD_];
__device__ h16   g_sT [NHEADS * HD_ * HD_];
__device__ h16   g_a  [(size_t)MTOT * E_];

// =========================== helpers ==============================================
__device__ __forceinline__ uint32_t smem_u32(const void* p) {
    return (uint32_t)__cvta_generic_to_shared(p);
}
__device__ __forceinline__ uint32_t pack2h(h16 a, h16 b) {
    return (uint32_t)__half_as_ushort(a) | ((uint32_t)__half_as_ushort(b) << 16);
}

#define CP_COMMIT() asm volatile("cp.async.commit_group;" ::: "memory")
#define CP_WAIT(n)  asm volatile("cp.async.wait_group %0;" :: "n"(n) : "memory")

__device__ __forceinline__ void cpa16(uint32_t s, const void* g) {
    asm volatile("cp.async.cg.shared.global [%0], [%1], 16;" :: "r"(s), "l"(g));
}
__device__ __forceinline__ void ldsm4(uint32_t (&r)[4], uint32_t a) {
    asm volatile("ldmatrix.sync.aligned.m8n8.x4.shared.b16 {%0,%1,%2,%3}, [%4];"
                 : "=r"(r[0]), "=r"(r[1]), "=r"(r[2]), "=r"(r[3]) : "r"(a));
}
__device__ __forceinline__ void mma_f16(float (&c)[4], const uint32_t (&a)[4],
                                        uint32_t b0, uint32_t b1) {
    asm volatile("mma.sync.aligned.m16n8k16.row.col.f32.f16.f16.f32 "
        "{%0,%1,%2,%3}, {%4,%5,%6,%7}, {%8,%9}, {%0,%1,%2,%3};"
        : "+f"(c[0]), "+f"(c[1]), "+f"(c[2]), "+f"(c[3])
        : "r"(a[0]), "r"(a[1]), "r"(a[2]), "r"(a[3]), "r"(b0), "r"(b1));
}

// =========================== mma GEMM machinery ===================================
// Templated on MI (A-fragment rows per warp / 16): block tile (MI*32) x 128 x 64.
// 8 warps as 2(M) x 4(N); warp tile (MI*16) x 32. SW128 XOR-swizzled smem.
__device__ __forceinline__ uint32_t swz(uint32_t row, uint32_t cb) {
    return row * 128 + (cb ^ ((row & 7) << 4));
}
template<int R>
__device__ __forceinline__ void load_tileR(uint32_t sbase, const h16* g, int ldg, int tid) {
    #pragma unroll
    for (int t = 0; t < R / 32; t++) {
        int idx = tid + t * 256;
        int r = idx >> 3, c = idx & 7;
        cpa16(sbase + swz(r, c * 16), g + (size_t)r * ldg + c * 8);
    }
}
template<int MI>
__device__ __forceinline__ void stage_load(uint32_t sbase,
    const h16* A, int lda, const h16* Bs, int ldb, int tid)
{
    load_tileR<MI * 32>(sbase, A, lda, tid);
    load_tileR<128>(sbase + MI * 4096, Bs, ldb, tid);
}

template<int MI>
__device__ __forceinline__ void compute_stage(uint32_t sbase, int wm, int wn, int lane,
                                              float (&acc)[MI][4][4])
{
    const uint32_t sA = sbase, sB = sbase + MI * 4096;
    const int arow = wm * (MI * 16) + (lane & 15);
    const uint32_t acbx = (lane & 16) ? 16 : 0;
    const int brow = wn * 32 + (lane & 7) + ((lane & 16) ? 8 : 0);
    const uint32_t bcbx = (lane & 8) ? 16 : 0;

    #pragma unroll
    for (int kk = 0; kk < 4; kk++) {
        const uint32_t acb = kk * 32 + acbx, bcb = kk * 32 + bcbx;
        uint32_t bb[2][4];
        #pragma unroll
        for (int nj2 = 0; nj2 < 2; nj2++)
            ldsm4(bb[nj2], sB + swz(brow + nj2 * 16, bcb));
        #pragma unroll
        for (int mi = 0; mi < MI; mi++) {
            uint32_t aa[4];
            ldsm4(aa, sA + swz(arow + mi * 16, acb));
            #pragma unroll
            for (int nj = 0; nj < 4; nj++) {
                const int j2 = nj >> 1, jo = (nj & 1) * 2;
                mma_f16(acc[mi][nj], aa, bb[j2][jo], bb[j2][jo + 1]);
            }
        }
    }
}

// ---- classic BK=64 multi-stage loop (kept for ktk) ----
template<int MI, int NST>
__device__ __forceinline__ void run_mainloop(uint32_t sm,
    const h16* pA, int lda, const h16* pB, int ldb, int KT,
    int wm, int wn, int lane, int tid, float (&acc)[MI][4][4])
{
    const uint32_t SB = MI * 4096 + 16384;
    #pragma unroll
    for (int p = 0; p < NST - 1; p++) {
        if (p < KT)
            stage_load<MI>(sm + p * SB, pA + p * 64, lda, pB + p * 64, ldb, tid);
        CP_COMMIT();
    }
    for (int i = 0; i < KT; i++) {
        CP_WAIT(NST - 2);
        __syncthreads();
        if (i + NST - 1 < KT) {
            const int k0 = (i + NST - 1) * 64, slot = (i + NST - 1) % NST;
            stage_load<MI>(sm + slot * SB, pA + k0, lda, pB + k0, ldb, tid);
        }
        CP_COMMIT();
        compute_stage<MI>(sm + (i % NST) * SB, wm, wn, lane, acc);
    }
}

// ---- BK=128 two-slot ping-pong loop (big GEMMs + attn) ----
// Stage = two back-to-back BK=64 half-stages (2 commit groups each).
template<int MI>
__device__ __forceinline__ void run_mainloop_bk128(uint32_t sm,
    const h16* pA, int lda, const h16* pB, int ldb, int KT2,
    int wm, int wn, int lane, int tid, float (&acc)[MI][4][4])
{
    const uint32_t HB = MI * 4096 + 16384;   // half-stage bytes
    const uint32_t SB = 2 * HB;              // full stage (BK=128)
    stage_load<MI>(sm,      pA,      lda, pB,      ldb, tid); CP_COMMIT();
    stage_load<MI>(sm + HB, pA + 64, lda, pB + 64, ldb, tid); CP_COMMIT();
    if (KT2 > 1) {
        stage_load<MI>(sm + SB,      pA + 128, lda, pB + 128, ldb, tid); CP_COMMIT();
        stage_load<MI>(sm + SB + HB, pA + 192, lda, pB + 192, ldb, tid); CP_COMMIT();
    } else { CP_COMMIT(); CP_COMMIT(); }
    for (int i = 0; i < KT2; i++) {
        CP_WAIT(2);              // stage i's two groups retired
        __syncthreads();         // visibility of all threads' cp.async data
        const uint32_t base = sm + (i & 1) * SB;
        compute_stage<MI>(base, wm, wn, lane, acc);
        compute_stage<MI>(base + HB, wm, wn, lane, acc);
        __syncthreads();         // all warps done reading this slot
        if (i + 2 < KT2) {
            const int k0 = (i + 2) * 128;
            stage_load<MI>(base,      pA + k0,      lda, pB + k0,      ldb, tid); CP_COMMIT();
            stage_load<MI>(base + HB, pA + k0 + 64, lda, pB + k0 + 64, ldb, tid); CP_COMMIT();
        } else { CP_COMMIT(); CP_COMMIT(); }
    }
}

#define ACC_INIT(acc, MI) \
    _Pragma("unroll") for (int a_ = 0; a_ < (MI); a_++) \
    _Pragma("unroll") for (int b_ = 0; b_ < 4; b_++) \
    _Pragma("unroll") for (int c_ = 0; c_ < 4; c_++) acc[a_][b_][c_] = 0.f;

// =========================== conversion kernels ===================================
__global__ void conv_h_kernel(const float* __restrict__ in) {
    size_t i = ((size_t)blockIdx.x * 256 + threadIdx.x) * 4;
    float4 v = *(const float4*)(in + i);
    *(uint2*)(g_x + i) = make_uint2(
        pack2h(__float2half_rn(v.x), __float2half_rn(v.y)),
        pack2h(__float2half_rn(v.z), __float2half_rn(v.w)));
}

__global__ void conv_T_kernel(const float* __restrict__ W0, const float* __restrict__ W1,
                              const float* __restrict__ W2, const float* __restrict__ W3) {
    __shared__ float t[32][33];
    const int z = blockIdx.z;
    const float* W = (z == 0) ? W0 : (z == 1) ? W1 : (z == 2) ? W2 : W3;
    h16* wt = (z == 0) ? g_wq : (z == 1) ? g_wk : (z == 2) ? g_wv : g_wf;
    const int n0 = blockIdx.x * 32, k0 = blockIdx.y * 32;
    const int tx = threadIdx.x, ty = threadIdx.y;
    #pragma unroll
    for (int j = 0; j < 4; j++)
        t[ty + 8 * j][tx] = W[(size_t)(k0 + ty + 8 * j) * E_ + n0 + tx];
    __syncthreads();
    #pragma unroll
    for (int j = 0; j < 4; j++)
        wt[(size_t)(n0 + ty + 8 * j) * E_ + k0 + tx] = __float2half_rn(t[tx][ty + 8 * j]);
}

// =========================== fused QKV GEMM (BM=256, BK=128) ======================
// z=0: Q -> row-major fp16; z=1: K -> transposed fp16; z=2: V -> transposed fp16
__global__ __launch_bounds__(256, 1) void gemm_qkv(
    const float* __restrict__ bq, const float* __restrict__ bk,
    const float* __restrict__ bv)
{
    extern __shared__ char smraw[];
    const uint32_t sm = (smem_u32(smraw) + 127) & ~127u;
    const int tid = threadIdx.x, lane = tid & 31, wid = tid >> 5;
    const int wm = wid >> 2, wn = wid & 3;
    const int m0 = blockIdx.y * 256, n0 = blockIdx.x * 128;
    const int z = blockIdx.z;

    const h16* Bp = (z == 0) ? g_wq : (z == 1) ? g_wk : g_wv;
    const float* bias = (z == 0) ? bq : (z == 1) ? bk : bv;

    float acc[8][4][4];
    ACC_INIT(acc, 8)

    run_mainloop_bk128<8>(sm, g_x + (size_t)m0 * E_, E_, Bp + (size_t)n0 * E_, E_,
                          E_ / 128, wm, wn, lane, tid, acc);

    const int rb = wm * 128 + (lane >> 2);
    const int cb = wn * 32 + (lane & 3) * 2;

    if (z == 0) {
        #pragma unroll
        for (int mi = 0; mi < 8; mi++)
            #pragma unroll
            for (int nj = 0; nj < 4; nj++) {
                const int r = m0 + rb + mi * 16;
                const int c = n0 + cb + nj * 8;
                const float b0 = bias[c], b1 = bias[c + 1];
                *(uint32_t*)(g_q + (size_t)r * E_ + c) =
                    pack2h(__float2half_rn(acc[mi][nj][0] + b0),
                           __float2half_rn(acc[mi][nj][1] + b1));
                *(uint32_t*)(g_q + (size_t)(r + 8) * E_ + c) =
                    pack2h(__float2half_rn(acc[mi][nj][2] + b0),
                           __float2half_rn(acc[mi][nj][3] + b1));
            }
        return;
    }

    // transposed epilogue via smem bounce: 256 rows(s) x 128 cols(e), pitch 129
    __syncthreads();
    float* sT = (float*)(smraw) + 32;
    #pragma unroll
    for (int mi = 0; mi < 8; mi++)
        #pragma unroll
        for (int nj = 0; nj < 4; nj++) {
            const int r = rb + mi * 16;
            const int c = cb + nj * 8;
            const float b0 = bias[n0 + c], b1 = bias[n0 + c + 1];
            sT[r * 129 + c]           = acc[mi][nj][0] + b0;
            sT[r * 129 + c + 1]       = acc[mi][nj][1] + b1;
            sT[(r + 8) * 129 + c]     = acc[mi][nj][2] + b0;
            sT[(r + 8) * 129 + c + 1] = acc[mi][nj][3] + b1;
        }
    __syncthreads();

    h16* dst = (z == 1) ? g_Kt : g_Vt;
    const int e = tid >> 1, sh = (tid & 1) * 128;
    const int bB = m0 / S_, sInB = (m0 % S_) + sh;
    const size_t grow = ((size_t)(bB * E_ + n0 + e)) * S_ + sInB;

    uint32_t hw[64];
    #pragma unroll
    for (int q = 0; q < 64; q++) {
        float v0 = sT[(sh + 2 * q) * 129 + e];
        float v1 = sT[(sh + 2 * q + 1) * 129 + e];
        hw[q] = pack2h(__float2half_rn(v0), __float2half_rn(v1));
    }
    #pragma unroll
    for (int q = 0; q < 16; q++)
        *(uint4*)(dst + grow + q * 8) = make_uint4(hw[q*4], hw[q*4+1], hw[q*4+2], hw[q*4+3]);
}

// =========================== final GEMM (BM=256, BK=128) ==========================
__global__ __launch_bounds__(256, 1) void gemm_fc(const float* __restrict__ bias,
                                                  float* __restrict__ outF)
{
    extern __shared__ char smraw[];
    const uint32_t sm = (smem_u32(smraw) + 127) & ~127u;
    const int tid = threadIdx.x, lane = tid & 31, wid = tid >> 5;
    const int wm = wid >> 2, wn = wid & 3;
    const int m0 = blockIdx.y * 256, n0 = blockIdx.x * 128;

    float acc[8][4][4];
    ACC_INIT(acc, 8)

    run_mainloop_bk128<8>(sm, g_a + (size_t)m0 * E_, E_, g_wf + (size_t)n0 * E_, E_,
                          E_ / 128, wm, wn, lane, tid, acc);

    const int row_base = m0 + wm * 128 + (lane >> 2);
    const int col_base = n0 + wn * 32 + (lane & 3) * 2;
    #pragma unroll
    for (int mi = 0; mi < 8; mi++)
        #pragma unroll
        for (int nj = 0; nj < 4; nj++) {
            const int r = row_base + mi * 16;
            const int c = col_base + nj * 8;
            const float b0 = bias[c], b1 = bias[c + 1];
            *(float2*)(outF + (size_t)r * E_ + c) =
                make_float2(acc[mi][nj][0] + b0, acc[mi][nj][1] + b1);
            *(float2*)(outF + (size_t)(r + 8) * E_ + c) =
                make_float2(acc[mi][nj][2] + b0, acc[mi][nj][3] + b1);
        }
}

// =========================== K^T K / K^T V (split-K x4, MI=4) =====================
__global__ __launch_bounds__(256, 1) void ktk_mma()
{
    extern __shared__ char smraw[];
    const uint32_t sm = (smem_u32(smraw) + 127) & ~127u;
    const int tid = threadIdx.x, lane = tid & 31, wid = tid >> 5;
    const int wm = wid >> 2, wn = wid & 3;
    const int head = blockIdx.x, which = blockIdx.y, ks = blockIdx.z;

    const size_t hb = (size_t)head * HD_ * S_ + ks * (S_ / KSPLIT);
    const h16* pA = g_Kt + hb;
    const h16* pB = (which ? g_Vt : g_Kt) + hb;
    float* out = (which ? g_ktvp : g_kkp) + ((size_t)ks * NHEADS + head) * HD_ * HD_;

    float acc[4][4][4];
    ACC_INIT(acc, 4)

    run_mainloop<4, 6>(sm, pA, S_, pB, S_, (S_ / KSPLIT) / 64, wm, wn, lane, tid, acc);

    const int row_base = wm * 64 + (lane >> 2);
    const int col_base = wn * 32 + (lane & 3) * 2;
    #pragma unroll
    for (int mi = 0; mi < 4; mi++)
        #pragma unroll
        for (int nj = 0; nj < 4; nj++) {
            const int r = row_base + mi * 16;
            const int c = col_base + nj * 8;
            *(float2*)(out + (size_t)r * HD_ + c) =
                make_float2(acc[mi][nj][0], acc[mi][nj][1]);
            *(float2*)(out + (size_t)(r + 8) * HD_ + c) =
                make_float2(acc[mi][nj][2], acc[mi][nj][3]);
        }
}

// =========================== solve + softmax (fp32 SIMT) ==========================
#define LDAUG 257
__global__ __launch_bounds__(256) void solve_softmax_kernel(const float* __restrict__ alpha)
{
    extern __shared__ float sAug[];
    __shared__ float facs[128];
    const int head = blockIdx.x;
    const int tid = threadIdx.x;
    const size_t hoff = (size_t)head * HD_ * HD_;
    const size_t pstride = (size_t)NHEADS * HD_ * HD_;
    const float a = alpha[0];

    for (int idx = tid; idx < HD_ * HD_; idx += 256) {
        int r = idx >> 7, c = idx & 127;
        float skk  = g_kkp [hoff + idx] + g_kkp [pstride + hoff + idx]
                   + g_kkp [2 * pstride + hoff + idx] + g_kkp [3 * pstride + hoff + idx];
        float sktv = g_ktvp[hoff + idx] + g_ktvp[pstride + hoff + idx]
                   + g_ktvp[2 * pstride + hoff + idx] + g_ktvp[3 * pstride + hoff + idx];
        sAug[r * LDAUG + c]       = skk + (r == c ? a : 0.f);
        sAug[r * LDAUG + 128 + c] = sktv;
    }
    __syncthreads();

    for (int k = 0; k < HD_; k++) {
        if (tid < 128) facs[tid] = sAug[tid * LDAUG + k];
        __syncthreads();
        float pivc = sAug[k * LDAUG + tid] / facs[k];
        sAug[k * LDAUG + tid] = pivc;
        __syncthreads();
        #pragma unroll 4
        for (int r = 0; r < HD_; r++)
            if (r != k) sAug[r * LDAUG + tid] -= facs[r] * pivc;
        __syncthreads();
    }

    const int warp = tid >> 5, lane = tid & 31;
    for (int r = warp; r < HD_; r += 8) {
        float vals[4];
        float mx = -1e30f;
        #pragma unroll
        for (int t = 0; t < 4; t++) {
            vals[t] = sAug[r * LDAUG + 128 + lane + 32 * t];
            mx = fmaxf(mx, vals[t]);
        }
        #pragma unroll
        for (int o = 16; o; o >>= 1) mx = fmaxf(mx, __shfl_xor_sync(0xffffffffu, mx, o));
        float sum = 0.f;
        #pragma unroll
        for (int t = 0; t < 4; t++) { vals[t] = expf(vals[t] - mx); sum += vals[t]; }
        #pragma unroll
        for (int o = 16; o; o >>= 1) sum += __shfl_xor_sync(0xffffffffu, sum, o);
        float inv = 1.f / sum;
        #pragma unroll
        for (int t = 0; t < 4; t++) {
            int e = lane + 32 * t;
            g_sT[hoff + e * HD_ + r] = __float2half_rn(vals[t] * inv);  // score^T[e][d=r]
        }
    }
}

// =========================== attn = Q @ score (BM=256, K=128 single stage) ========
__global__ __launch_bounds__(256, 1) void attn_mma()
{
    extern __shared__ char smraw[];
    const uint32_t sm = (smem_u32(smraw) + 127) & ~127u;
    const int tid = threadIdx.x, lane = tid & 31, wid = tid >> 5;
    const int wm = wid >> 2, wn = wid & 3;
    const int head = blockIdx.x, stile = blockIdx.y;
    const int bb = head >> 4, h = head & 15;
    const size_t arow0 = (size_t)(bb * S_ + stile * 256);

    const h16* pA = g_q + arow0 * E_ + h * 128;
    const h16* pB = g_sT + (size_t)head * HD_ * HD_;

    float acc[8][4][4];
    ACC_INIT(acc, 8)

    run_mainloop_bk128<8>(sm, pA, E_, pB, HD_, 1, wm, wn, lane, tid, acc);

    const int row_base = wm * 128 + (lane >> 2);
    const int col_base = h * 128 + wn * 32 + (lane & 3) * 2;
    #pragma unroll
    for (int mi = 0; mi < 8; mi++)
        #pragma unroll
        for (int nj = 0; nj < 4; nj++) {
            const size_t r = arow0 + row_base + mi * 16;
            const int c = col_base + nj * 8;
            *(uint32_t*)(g_a + r * E_ + c) =
                pack2h(__float2half_rn(acc[mi][nj][0]), __float2half_rn(acc[mi][nj][1]));
            *(uint32_t*)(g_a + (r + 8) * E_ + c) =
                pack2h(__float2half_rn(acc[mi][nj][2]), __float2half_rn(acc[mi][nj][3]));
        }
}

// =================================================================================
extern "C" void kernel_launch(void* const* d_in, const int* in_sizes, int n_in,
                              void* d_out, int out_size)
{
    (void)in_sizes; (void)n_in; (void)out_size;
    const float* x     = (const float*)d_in[0];
    const float* alpha = (const float*)d_in[1];
    const float* Wq    = (const float*)d_in[2];
    const float* bq    = (const float*)d_in[3];
    const float* Wk    = (const float*)d_in[4];
    const float* bk    = (const float*)d_in[5];
    const float* Wv    = (const float*)d_in[6];
    const float* bv    = (const float*)d_in[7];
    const float* Wfc   = (const float*)d_in[8];
    const float* bfc   = (const float*)d_in[9];
    float* out = (float*)d_out;

    const int SMEM_BIG = 2 * 2 * (8 * 4096 + 16384) + 1024;   // 197632 (2 x BK128 slots)
    const int SMEM_ATT = 2 * (8 * 4096 + 16384) + 1024;       //  99328 (1 slot)
    const int SMEM_KTK = 6 * (4 * 4096 + 16384) + 1024;       // 197632 (MI=4, 6 stages)
    const int SMEM_S   = 128 * LDAUG * 4;                     // 131584
    cudaFuncSetAttribute(gemm_qkv, cudaFuncAttributeMaxDynamicSharedMemorySize, SMEM_BIG);
    cudaFuncSetAttribute(gemm_fc,  cudaFuncAttributeMaxDynamicSharedMemorySize, SMEM_BIG);
    cudaFuncSetAttribute(ktk_mma,  cudaFuncAttributeMaxDynamicSharedMemorySize, SMEM_KTK);
    cudaFuncSetAttribute(attn_mma, cudaFuncAttributeMaxDynamicSharedMemorySize, SMEM_ATT);
    cudaFuncSetAttribute(solve_softmax_kernel, cudaFuncAttributeMaxDynamicSharedMemorySize, SMEM_S);

    // 1) x -> fp16
    conv_h_kernel<<<(int)((size_t)MTOT * E_ / 4 / 256), 256>>>(x);
    // 2) transpose weights -> [N x K] fp16 (all 4 in one launch)
    dim3 tb(32, 8), tg(E_ / 32, E_ / 32, 4);
    conv_T_kernel<<<tg, tb>>>(Wq, Wk, Wv, Wfc);
    // 3) fused Q/K/V projections, BM=256 BK=128 (K,V written transposed directly)
    gemm_qkv<<<dim3(E_ / 128, MTOT / 256, 3), 256, SMEM_BIG>>>(bq, bk, bv);
    // 4) K^T K and K^T V (split-K x4 into partials)
    ktk_mma<<<dim3(NHEADS, 2, KSPLIT), 256, SMEM_KTK>>>();
    // 5) solve + softmax -> score^T fp16; sums partials on load
    solve_softmax_kernel<<<NHEADS, 256, SMEM_S>>>(alpha);
    // 6) attn = Q @ score, BM=256, single K-stage
    attn_mma<<<dim3(NHEADS, S_ / 256), 256, SMEM_ATT>>>();
    // 7) output projection, BM=256 BK=128
    gemm_fc<<<dim3(E_ / 128, MTOT / 256), 256, SMEM_BIG>>>(bfc, out);
}